// round 4
// baseline (speedup 1.0000x reference)
#include <cuda_runtime.h>

// Fixed shapes: B=16, C=256, H=W=80 -> L=6400 per (b,c) row, 4096 rows.
#define L_LEN    6400
#define NTH      800          // threads per row-CTA (25 warps)
#define CHUNK    8            // L_LEN / NTH, two float4 groups per thread
#define NWARPS   25
#define C_CH     256
#define ALPHA_F  0.1f
#define EPS_F    1e-7f

// Per-launch recomputed tables (__device__ globals = legal scratch).
__device__ float g_inv[L_LEN];   // 1 / (cumsum(alpha*0.9^j) + eps) via closed form
__device__ float g_w0[NTH];      // alpha * 0.9^(CHUNK*t) chunk-start anchors

// ---------------- setup: closed-form tables, fully parallel, no scan ----------------
// cumsum_{j<=i}(alpha*0.9^j) = 1 - 0.9^(i+1)   (geometric series, alpha = 1-0.9)
__global__ void ema_setup_kernel() {
    const int i = blockIdx.x * blockDim.x + threadIdx.x;
    if (i < L_LEN) {
        const float d = powf(0.9f, (float)(i + 1));
        g_inv[i] = 1.0f / ((1.0f + EPS_F) - d);
    }
    if (i < NTH)
        g_w0[i] = ALPHA_F * powf(0.9f, (float)(CHUNK * i));
}

// ---------------- main kernel: one CTA per (b,c) row, register-resident ----------------
__global__ void __launch_bounds__(NTH, 2)
ema_main_kernel(const float* __restrict__ x,
                const float* __restrict__ conv_w,
                const float* __restrict__ conv_b,
                float* __restrict__ out) {
    __shared__ float ws[32];            // padded to 32 for clean lane indexing

    const int row  = blockIdx.x;
    const int c    = row & (C_CH - 1);
    const int t    = threadIdx.x;
    const int lane = t & 31;
    const int wid  = t >> 5;
    const int i0   = t * CHUNK;

    const float* __restrict__ xr   = x   + (size_t)row * L_LEN;
    float*       __restrict__ outr = out + (size_t)row * L_LEN;

    // 8 contiguous elements -> registers (2x aligned LDG.128)
    float xv[CHUNK];
    {
        const float4* x4 = reinterpret_cast<const float4*>(xr + i0);
        float4 a = __ldg(x4 + 0);
        float4 b = __ldg(x4 + 1);
        xv[0]=a.x; xv[1]=a.y; xv[2]=a.z; xv[3]=a.w;
        xv[4]=b.x; xv[5]=b.y; xv[6]=b.z; xv[7]=b.w;
    }

    // Conv neighbors from adjacent threads' registers via shuffle; warp edges via LDG.
    float leftN  = __shfl_up_sync(0xffffffffu,  xv[CHUNK - 1], 1);
    float rightN = __shfl_down_sync(0xffffffffu, xv[0], 1);
    if (lane == 0)  leftN  = (t == 0)       ? 0.f : __ldg(xr + i0 - 1);
    if (lane == 31) rightN = (t == NTH - 1) ? 0.f : __ldg(xr + i0 + CHUNK);

    const float w0   = __ldg(&conv_w[c * 3 + 0]);
    const float w1   = __ldg(&conv_w[c * 3 + 1]);
    const float w2   = __ldg(&conv_w[c * 3 + 2]);
    const float bias = __ldg(&conv_b[c]);
    const float wstart = __ldg(&g_w0[t]);   // alpha * 0.9^i0

    // Phase A: chunk sum of weighted terms (weights via 0.9 recurrence, no loads)
    float s = 0.f, w = wstart;
    #pragma unroll
    for (int k = 0; k < CHUNK; k++) {
        s = fmaf(xv[k], w, s);
        w *= 0.9f;
    }

    // Block exclusive scan, ONE barrier, two-level shuffle scan (no per-thread loop):
    float inc = s;
    #pragma unroll
    for (int off = 1; off < 32; off <<= 1) {
        float y = __shfl_up_sync(0xffffffffu, inc, off);
        if (lane >= off) inc += y;
    }
    if (lane == 31) ws[wid] = inc;
    __syncthreads();
    // every warp redundantly scans the 25 warp sums in-register
    float wv = (lane < NWARPS) ? ws[lane] : 0.f;
    #pragma unroll
    for (int off = 1; off < 32; off <<= 1) {
        float y = __shfl_up_sync(0xffffffffu, wv, off);
        if (lane >= off) wv += y;
    }
    float wprefix = __shfl_sync(0xffffffffu, wv, (wid == 0) ? 0 : wid - 1);
    if (wid == 0) wprefix = 0.f;
    float run = wprefix + inc - s;       // exclusive prefix for this thread

    // Phase B: ema + depthwise conv + residual; 4-wide groups -> STG.128
    w = wstart;
    float xp = leftN;
    #pragma unroll
    for (int g = 0; g < CHUNK / 4; g++) {
        const float4 inv4 = __ldg(reinterpret_cast<const float4*>(&g_inv[i0 + g*4]));
        const float iv[4] = {inv4.x, inv4.y, inv4.z, inv4.w};
        float o[4];
        #pragma unroll
        for (int q = 0; q < 4; q++) {
            const int k = g*4 + q;
            const float xc = xv[k];
            const float xn = (k == CHUNK - 1) ? rightN : xv[k + 1];
            run = fmaf(xc, w, run);
            w *= 0.9f;
            const float ema  = run * iv[q];
            const float conv = fmaf(w0, xp, fmaf(w1, xc, fmaf(w2, xn, bias)));
            o[q] = xc + ema + conv;
            xp = xc;
        }
        *reinterpret_cast<float4*>(outr + i0 + g*4) = make_float4(o[0], o[1], o[2], o[3]);
    }
}

extern "C" void kernel_launch(void* const* d_in, const int* in_sizes, int n_in,
                              void* d_out, int out_size) {
    const float* x      = (const float*)d_in[0];  // [16,256,80,80]
    const float* conv_w = (const float*)d_in[1];  // [256,1,3]
    const float* conv_b = (const float*)d_in[2];  // [256]
    float* out = (float*)d_out;

    ema_setup_kernel<<<(L_LEN + 255) / 256, 256>>>();
    ema_main_kernel<<<16 * C_CH, NTH>>>(x, conv_w, conv_b, out);
}

// round 9
// speedup vs baseline: 1.7009x; 1.7009x over previous
#include <cuda_runtime.h>

// Fixed shapes: B=16, C=256, H=W=80 -> L=6400 per row, 4096 rows.
// EMA insight: weights alpha*0.9^j vanish past j~250, so
//   prefix_i ≈ S = sum_{j<256} x_j*alpha*0.9^j  for all i>=256, and
//   denom_i  = 1 - 0.9^(i+1) + eps  -> (1+eps) exactly in fp32 for i>=256.
// => ema is a per-row CONSTANT except for the first 256 elements.
#define L_LEN    6400
#define C_CH     256
#define SLICES   25          // 6400 / 256 elements per warp-slice
#define WPC      8           // warps per CTA
#define NTH      (WPC * 32)
#define ALPHA_F  0.1f
#define EPS_F    1e-7f
#define LOG2_09  (-0.15200309344504997f)   // log2(0.9)

__global__ void __launch_bounds__(NTH)
ema_kernel(const float* __restrict__ x,
           const float* __restrict__ conv_w,
           const float* __restrict__ conv_b,
           float* __restrict__ out) {
    const int lane = threadIdx.x & 31;
    const int gw   = blockIdx.x * WPC + (threadIdx.x >> 5);  // global warp id
    const int row  = gw / SLICES;
    const int sl   = gw - row * SLICES;
    const int c    = row & (C_CH - 1);

    const float* __restrict__ xr   = x   + (size_t)row * L_LEN;
    float*       __restrict__ outr = out + (size_t)row * L_LEN;
    const int e0 = sl * 256 + lane * 8;          // this lane's 8 slice elements

    // ---- batched loads up front (max MLP) ----
    // Row head x[0..255] (8/lane): shared by all warps of the row -> L1/L2 broadcast.
    float hv[8];
    {
        const float4* h4 = reinterpret_cast<const float4*>(xr) + 2 * lane;
        const float4 a = __ldg(h4), b = __ldg(h4 + 1);
        hv[0]=a.x; hv[1]=a.y; hv[2]=a.z; hv[3]=a.w;
        hv[4]=b.x; hv[5]=b.y; hv[6]=b.z; hv[7]=b.w;
    }
    // This warp's slice values (identical to head when sl==0).
    float xv[8];
    if (sl == 0) {
        #pragma unroll
        for (int k = 0; k < 8; k++) xv[k] = hv[k];
    } else {
        const float4* s4 = reinterpret_cast<const float4*>(xr + e0);
        const float4 a = __ldg(s4), b = __ldg(s4 + 1);
        xv[0]=a.x; xv[1]=a.y; xv[2]=a.z; xv[3]=a.w;
        xv[4]=b.x; xv[5]=b.y; xv[6]=b.z; xv[7]=b.w;
    }

    // Conv neighbors via shuffle; slice edges via scalar loads (L1/L2 hits).
    float leftN  = __shfl_up_sync(0xffffffffu,  xv[7], 1);
    float rightN = __shfl_down_sync(0xffffffffu, xv[0], 1);
    if (lane == 0)  leftN  = (sl == 0)          ? 0.f : __ldg(xr + e0 - 1);
    if (lane == 31) rightN = (sl == SLICES - 1) ? 0.f : __ldg(xr + e0 + 8);

    const float w0   = __ldg(&conv_w[c * 3 + 0]);
    const float w1   = __ldg(&conv_w[c * 3 + 1]);
    const float w2   = __ldg(&conv_w[c * 3 + 2]);
    const float bias = __ldg(&conv_b[c]);

    // Weighted head sum: lane l covers j = 8l..8l+7, weight alpha*0.9^j.
    const float wl = ALPHA_F * exp2f((float)(8 * lane) * LOG2_09);
    float s = 0.f, w = wl;
    #pragma unroll
    for (int k = 0; k < 8; k++) { s = fmaf(hv[k], w, s); w *= 0.9f; }

    if (sl == 0) {
        // --- head warp: exact per-element EMA via 5-shfl exclusive warp scan ---
        float inc = s;
        #pragma unroll
        for (int off = 1; off < 32; off <<= 1) {
            const float y = __shfl_up_sync(0xffffffffu, inc, off);
            if (lane >= off) inc += y;
        }
        float run = inc - s;                     // exclusive prefix of lane sums
        float ww = wl;
        float d  = 9.0f * wl;                    // 0.9^(i+1) at i = 8*lane (= 10*wl*0.9)
        float xp = leftN;
        #pragma unroll
        for (int g = 0; g < 2; g++) {
            float o[4];
            #pragma unroll
            for (int q = 0; q < 4; q++) {
                const int k = g * 4 + q;
                const float xc = xv[k];
                const float xn = (k == 7) ? rightN : xv[k + 1];
                run = fmaf(xc, ww, run); ww *= 0.9f;
                const float ema  = __fdividef(run, (1.0f + EPS_F) - d); d *= 0.9f;
                const float conv = fmaf(w0, xp, fmaf(w1, xc, fmaf(w2, xn, bias)));
                o[q] = xc + ema + conv;
                xp = xc;
            }
            *reinterpret_cast<float4*>(outr + e0 + g * 4) =
                make_float4(o[0], o[1], o[2], o[3]);
        }
    } else {
        // --- streaming warps: ema is the constant S/(1+eps) ---
        float S = s;
        #pragma unroll
        for (int off = 1; off < 32; off <<= 1)
            S += __shfl_xor_sync(0xffffffffu, S, off);
        const float emaC = S * (1.0f / (1.0f + EPS_F));
        float xp = leftN;
        #pragma unroll
        for (int g = 0; g < 2; g++) {
            float o[4];
            #pragma unroll
            for (int q = 0; q < 4; q++) {
                const int k = g * 4 + q;
                const float xc = xv[k];
                const float xn = (k == 7) ? rightN : xv[k + 1];
                const float conv = fmaf(w0, xp, fmaf(w1, xc, fmaf(w2, xn, bias)));
                o[q] = xc + emaC + conv;
                xp = xc;
            }
            *reinterpret_cast<float4*>(outr + e0 + g * 4) =
                make_float4(o[0], o[1], o[2], o[3]);
        }
    }
}

extern "C" void kernel_launch(void* const* d_in, const int* in_sizes, int n_in,
                              void* d_out, int out_size) {
    const float* x      = (const float*)d_in[0];  // [16,256,80,80]
    const float* conv_w = (const float*)d_in[1];  // [256,1,3]
    const float* conv_b = (const float*)d_in[2];  // [256]
    float* out = (float*)d_out;

    const int total_warps = 16 * C_CH * SLICES;   // 102400
    ema_kernel<<<total_warps / WPC, NTH>>>(x, conv_w, conv_b, out);
}

// round 12
// speedup vs baseline: 1.8844x; 1.1079x over previous
#include <cuda_runtime.h>

// Fixed shapes: B=16, C=256, H=W=80 -> L=6400 per row, 4096 rows.
// EMA math: weights alpha*0.9^j vanish past j~250 =>
//   prefix_i ≈ S = sum_{j<256} x_j*alpha*0.9^j  for all i>=256, and
//   denom_i -> (1+eps) exactly in fp32 for i>=256.
// => ema is a per-row CONSTANT except the first 256 elements (exact warp scan there).
#define L_LEN     6400
#define C_CH      256
#define WARPS_ROW 5            // warps per row
#define BLKS_WARP 5            // 256-element blocks per warp (5*5*256 = 6400)
#define SEG       1280         // elements per warp segment
#define WPC       8            // warps per CTA
#define NTH       (WPC * 32)
#define ALPHA_F   0.1f
#define EPS_F     1e-7f
#define LOG2_09   (-0.15200309344504997f)   // log2(0.9)

__global__ void __launch_bounds__(NTH)
ema_kernel(const float* __restrict__ x,
           const float* __restrict__ conv_w,
           const float* __restrict__ conv_b,
           float* __restrict__ out) {
    const int lane = threadIdx.x & 31;
    const int gw   = blockIdx.x * WPC + (threadIdx.x >> 5);   // global warp id
    const int row  = gw / WARPS_ROW;
    const int wseg = gw - row * WARPS_ROW;                    // 0..4
    const int c    = row & (C_CH - 1);

    const float* __restrict__ xr   = x   + (size_t)row * L_LEN;
    float*       __restrict__ outr = out + (size_t)row * L_LEN;
    const int base0 = wseg * SEG;                             // segment start

    // ---- first block's data (doubles as row head for wseg==0) ----
    float xv[8];
    {
        const float4* p = reinterpret_cast<const float4*>(xr + base0 + lane * 8);
        const float4 a = __ldg(p), b = __ldg(p + 1);
        xv[0]=a.x; xv[1]=a.y; xv[2]=a.z; xv[3]=a.w;
        xv[4]=b.x; xv[5]=b.y; xv[6]=b.z; xv[7]=b.w;
    }
    // Row head x[0..255] for S (reuse xv when this warp starts at 0).
    float hv[8];
    if (wseg == 0) {
        #pragma unroll
        for (int k = 0; k < 8; k++) hv[k] = xv[k];
    } else {
        const float4* h4 = reinterpret_cast<const float4*>(xr) + 2 * lane;
        const float4 a = __ldg(h4), b = __ldg(h4 + 1);
        hv[0]=a.x; hv[1]=a.y; hv[2]=a.z; hv[3]=a.w;
        hv[4]=b.x; hv[5]=b.y; hv[6]=b.z; hv[7]=b.w;
    }

    // Segment-edge conv neighbors. segLeft lives in lane 0, segRight lives in lane 31
    // (each lane uses only its OWN copy — no cross-lane broadcast of these).
    float segLeft = 0.f, segRight = 0.f;
    if (lane == 0  && wseg > 0)             segLeft  = __ldg(xr + base0 - 1);
    if (lane == 31 && wseg < WARPS_ROW - 1) segRight = __ldg(xr + base0 + SEG);

    const float w0   = __ldg(&conv_w[c * 3 + 0]);
    const float w1   = __ldg(&conv_w[c * 3 + 1]);
    const float w2   = __ldg(&conv_w[c * 3 + 2]);
    const float bias = __ldg(&conv_b[c]);

    // Weighted head sum: lane l covers j = 8l..8l+7 with weight alpha*0.9^j.
    const float wl = ALPHA_F * exp2f((float)(8 * lane) * LOG2_09);
    float s = 0.f, w = wl;
    #pragma unroll
    for (int k = 0; k < 8; k++) { s = fmaf(hv[k], w, s); w *= 0.9f; }

    // S: full-warp reduction (every lane needs it for the constant-EMA blocks).
    float S = s;
    #pragma unroll
    for (int off = 1; off < 32; off <<= 1)
        S += __shfl_xor_sync(0xffffffffu, S, off);
    const float emaC = S * (1.0f / (1.0f + EPS_F));

    float prevLast = segLeft;   // lane 0's left edge for the current block

    #pragma unroll
    for (int it = 0; it < BLKS_WARP; it++) {
        const int base = base0 + it * 256;

        // Prefetch next block before touching this one (keeps 2 loads in flight).
        float nx[8];
        if (it < BLKS_WARP - 1) {
            const float4* p = reinterpret_cast<const float4*>(xr + base + 256 + lane * 8);
            const float4 a = __ldg(p), b = __ldg(p + 1);
            nx[0]=a.x; nx[1]=a.y; nx[2]=a.z; nx[3]=a.w;
            nx[4]=b.x; nx[5]=b.y; nx[6]=b.z; nx[7]=b.w;
        }

        // Conv neighbors: intra-warp via shuffle; block edges via register broadcasts.
        float leftN  = __shfl_up_sync(0xffffffffu,  xv[7], 1);
        float rightN = __shfl_down_sync(0xffffffffu, xv[0], 1);
        // next block's first element lives in lane 0 of nx (valid only when it<last)
        const float nextFirst = __shfl_sync(0xffffffffu, nx[0], 0);
        if (lane == 0)  leftN  = prevLast;   // prev block's last (or segLeft / 0)
        if (lane == 31) rightN = (it < BLKS_WARP - 1) ? nextFirst : segRight;
        prevLast = __shfl_sync(0xffffffffu, xv[7], 31);

        if (wseg == 0 && it == 0) {
            // ---- exact EMA for elements 0..255 via 5-shfl exclusive warp scan ----
            float inc = s;
            #pragma unroll
            for (int off = 1; off < 32; off <<= 1) {
                const float y = __shfl_up_sync(0xffffffffu, inc, off);
                if (lane >= off) inc += y;
            }
            float run = inc - s;                      // exclusive prefix of lane sums
            float ww = wl;
            float d  = 9.0f * wl;                     // 0.9^(i+1) at i = 8*lane
            float xp = leftN;
            #pragma unroll
            for (int g = 0; g < 2; g++) {
                float o[4];
                #pragma unroll
                for (int q = 0; q < 4; q++) {
                    const int k = g * 4 + q;
                    const float xc = xv[k];
                    const float xn = (k == 7) ? rightN : xv[k + 1];
                    run = fmaf(xc, ww, run); ww *= 0.9f;
                    const float ema  = __fdividef(run, (1.0f + EPS_F) - d); d *= 0.9f;
                    const float conv = fmaf(w0, xp, fmaf(w1, xc, fmaf(w2, xn, bias)));
                    o[q] = xc + ema + conv;
                    xp = xc;
                }
                *reinterpret_cast<float4*>(outr + base + lane * 8 + g * 4) =
                    make_float4(o[0], o[1], o[2], o[3]);
            }
        } else {
            // ---- streaming block: ema is the row constant ----
            float xp = leftN;
            #pragma unroll
            for (int g = 0; g < 2; g++) {
                float o[4];
                #pragma unroll
                for (int q = 0; q < 4; q++) {
                    const int k = g * 4 + q;
                    const float xc = xv[k];
                    const float xn = (k == 7) ? rightN : xv[k + 1];
                    const float conv = fmaf(w0, xp, fmaf(w1, xc, fmaf(w2, xn, bias)));
                    o[q] = xc + emaC + conv;
                    xp = xc;
                }
                *reinterpret_cast<float4*>(outr + base + lane * 8 + g * 4) =
                    make_float4(o[0], o[1], o[2], o[3]);
            }
        }

        // Rotate prefetch into working registers.
        if (it < BLKS_WARP - 1) {
            #pragma unroll
            for (int k = 0; k < 8; k++) xv[k] = nx[k];
        }
    }
}

extern "C" void kernel_launch(void* const* d_in, const int* in_sizes, int n_in,
                              void* d_out, int out_size) {
    const float* x      = (const float*)d_in[0];  // [16,256,80,80]
    const float* conv_w = (const float*)d_in[1];  // [256,1,3]
    const float* conv_b = (const float*)d_in[2];  // [256]
    float* out = (float*)d_out;

    const int total_warps = 16 * C_CH * WARPS_ROW;    // 20480
    ema_kernel<<<total_warps / WPC, NTH>>>(x, conv_w, conv_b, out);
}